// round 13
// baseline (speedup 1.0000x reference)
#include <cuda_runtime.h>
#include <cuda_fp16.h>
#include <math.h>

#define N 16384
#define D 256
#define T 128
#define LOG2_097 (-0.04394334758759706f)

typedef unsigned int u32;
typedef unsigned long long u64;

// ---------------- scratch ---------------------------------------------------
__device__ float  g_V[T * D];      // gathered token embeddings fp32 [t][d]
__device__ __half g_Vh[T * D];     // V hi fp16 [t][k]
__device__ __half g_Vl[T * D];     // V lo (residual) fp16 [t][k]
__device__ __half g_cV[D * T];     // (0.97^(T-s)*V[s][d]) single fp16 [d][s]
__device__ __half g_Dyh[N * D];    // Dy in fp16
__device__ __half g_Eh[(size_t)D * N];  // E in fp16
__device__ __half g_yh[N];         // y in fp16
__device__ float  g_part2[128 * T];
__device__ float  g_lnA[D];
__device__ float  g_u[D];

// ---------------- helpers ----------------------------------------------------
__device__ __forceinline__ u32 s2u(const void* p) {
    u32 a;
    asm("{ .reg .u64 t; cvta.to.shared.u64 t, %1; cvt.u32.u64 %0, t; }" : "=r"(a) : "l"(p));
    return a;
}

#define LDSM_X4(r, addr)                                                        \
    asm volatile(                                                               \
        "ldmatrix.sync.aligned.m8n8.x4.shared.b16 {%0,%1,%2,%3}, [%4];"         \
        : "=r"((r)[0]), "=r"((r)[1]), "=r"((r)[2]), "=r"((r)[3])                \
        : "r"(addr))

__device__ __forceinline__ void mma16816(float* c, const u32* a, u32 b0, u32 b1) {
    asm volatile(
        "mma.sync.aligned.m16n8k16.row.col.f32.f16.f16.f32 "
        "{%0,%1,%2,%3}, {%4,%5,%6,%7}, {%8,%9}, {%0,%1,%2,%3};"
        : "+f"(c[0]), "+f"(c[1]), "+f"(c[2]), "+f"(c[3])
        : "r"(a[0]), "r"(a[1]), "r"(a[2]), "r"(a[3]), "r"(b0), "r"(b1));
}

// float4 -> 4 packed fp16 (u64)
__device__ __forceinline__ u64 to_h4(float4 v) {
    __half2 a = __floats2half2_rn(v.x, v.y);
    __half2 b = __floats2half2_rn(v.z, v.w);
    u32 ua = *(u32*)&a, ub = *(u32*)&b;
    return ((u64)ub << 32) | ua;
}

// ---------------- K0: convert Dy, E to fp16 ----------------------------------
__global__ __launch_bounds__(256) void k_cvt(const float* __restrict__ Dy,
                                             const float* __restrict__ E) {
    int b = blockIdx.x;
    const float* src = (b < 2048) ? Dy : E;
    __half* dst = (b < 2048) ? g_Dyh : g_Eh;
    size_t base = ((size_t)(b & 2047) * 256 + threadIdx.x) * 8;
    float4 a = *(const float4*)&src[base];
    float4 c = *(const float4*)&src[base + 4];
    __half2 h0 = __floats2half2_rn(a.x, a.y);
    __half2 h1 = __floats2half2_rn(a.z, a.w);
    __half2 h2 = __floats2half2_rn(c.x, c.y);
    __half2 h3 = __floats2half2_rn(c.z, c.w);
    uint4 o = make_uint4(*(u32*)&h0, *(u32*)&h1, *(u32*)&h2, *(u32*)&h3);
    *(uint4*)&dst[base] = o;
}

// ---------------- K1: gather + V splits + cV (fused prep) --------------------
__global__ __launch_bounds__(256) void k_prep(const float* __restrict__ temb,
                                              const int* __restrict__ toks) {
    int t = blockIdx.x, d = threadIdx.x;
    float v = temb[(size_t)toks[t] * D + d];
    g_V[t * D + d] = v;
    __half hv = __float2half_rn(v);
    g_Vh[t * D + d] = hv;
    g_Vl[t * D + d] = __float2half_rn(v - __half2float(hv));
    float c = exp2f((float)(T - t) * LOG2_097);
    g_cV[d * T + t] = __float2half_rn(c * v);
}

// ---------------- K2: FUSED GEMM1 + GEMM2 ------------------------------------
#define PA1 36
#define PA2 68
__global__ __launch_bounds__(512) void k_gemm12(const float* __restrict__ Dx,
                                                float* __restrict__ out) {
    extern __shared__ char sm[];
    const int S_A = 0, S_BH = 18432, S_BL = 36864;
    const int XBH = 69632, XBL = 104448, SCV = 139264;  // ends 208896
    int tid = threadIdx.x;
    int lane = tid & 31, wid = tid >> 5;
    int gr = lane >> 2, gc = lane & 3;
    int r8 = lane & 7, sub = lane >> 3;
    int n0 = blockIdx.x * 128;
    u32 smb = s2u(sm);

#pragma unroll
    for (int r = 0; r < 8; r++) {
        int gi = tid + 512 * r;
        int row = gi >> 4, j4 = gi & 15;
        *(uint4*)(sm + SCV + row * (PA2 * 4) + j4 * 16) = ((const uint4*)g_cV)[row * 16 + j4];
    }

    // ======================= PHASE A =======================
    {
        int m0w = (wid & 3) * 32;
        int t0 = (wid >> 2) * 32;

        float acc[2][4][4];
#pragma unroll
        for (int i = 0; i < 2; i++)
#pragma unroll
            for (int j = 0; j < 4; j++)
#pragma unroll
                for (int q = 0; q < 4; q++) acc[i][j][q] = 0.f;

        float4 pa[4];
        uint4 pbh[2], pbl[2];
#pragma unroll
        for (int r = 0; r < 4; r++) {
            int gi = tid + 512 * r;
            int row = gi >> 4, f4 = gi & 15;
            pa[r] = *(const float4*)&Dx[(size_t)(n0 + row) * D + f4 * 4];
        }
#pragma unroll
        for (int r = 0; r < 2; r++) {
            int gi = tid + 512 * r;
            int row = gi >> 3, j4 = gi & 7;
            pbh[r] = ((const uint4*)g_Vh)[row * 32 + j4];
            pbl[r] = ((const uint4*)g_Vl)[row * 32 + j4];
        }

        for (int c = 0; c < 4; c++) {
#pragma unroll
            for (int r = 0; r < 4; r++) {
                int gi = tid + 512 * r;
                int row = gi >> 4, f4 = gi & 15;
                *(u64*)(sm + S_A + row * (PA1 * 4) + f4 * 8) = to_h4(pa[r]);
            }
#pragma unroll
            for (int r = 0; r < 2; r++) {
                int gi = tid + 512 * r;
                int row = gi >> 3, j4 = gi & 7;
                *(uint4*)(sm + S_BH + row * (PA1 * 4) + j4 * 16) = pbh[r];
                *(uint4*)(sm + S_BL + row * (PA1 * 4) + j4 * 16) = pbl[r];
            }
            __syncthreads();
            if (c < 3) {
#pragma unroll
                for (int r = 0; r < 4; r++) {
                    int gi = tid + 512 * r;
                    int row = gi >> 4, f4 = gi & 15;
                    pa[r] = *(const float4*)&Dx[(size_t)(n0 + row) * D + (c + 1) * 64 + f4 * 4];
                }
#pragma unroll
                for (int r = 0; r < 2; r++) {
                    int gi = tid + 512 * r;
                    int row = gi >> 3, j4 = gi & 7;
                    pbh[r] = ((const uint4*)g_Vh)[row * 32 + (c + 1) * 8 + j4];
                    pbl[r] = ((const uint4*)g_Vl)[row * 32 + (c + 1) * 8 + j4];
                }
            }
#pragma unroll
            for (int ks = 0; ks < 4; ks++) {
                u32 ah[2][4], bh[2][4], bl[2][4];
#pragma unroll
                for (int mt = 0; mt < 2; mt++) {
                    int aw = (m0w + mt * 16 + r8 + (sub & 1) * 8) * PA1 + (sub >> 1) * 4 + ks * 8;
                    LDSM_X4(ah[mt], smb + S_A + aw * 4);
                }
#pragma unroll
                for (int g = 0; g < 2; g++) {
                    int bw = (t0 + g * 16 + r8 + (sub >> 1) * 8) * PA1 + (sub & 1) * 4 + ks * 8;
                    LDSM_X4(bh[g], smb + S_BH + bw * 4);
                    LDSM_X4(bl[g], smb + S_BL + bw * 4);
                }
#pragma unroll
                for (int g = 0; g < 2; g++)
#pragma unroll
                    for (int mt = 0; mt < 2; mt++) {
                        mma16816(acc[mt][2 * g], ah[mt], bh[g][0], bh[g][1]);
                        mma16816(acc[mt][2 * g + 1], ah[mt], bh[g][2], bh[g][3]);
                    }
#pragma unroll
                for (int g = 0; g < 2; g++)
#pragma unroll
                    for (int mt = 0; mt < 2; mt++) {
                        mma16816(acc[mt][2 * g], ah[mt], bl[g][0], bl[g][1]);
                        mma16816(acc[mt][2 * g + 1], ah[mt], bl[g][2], bl[g][3]);
                    }
            }
            __syncthreads();
        }

        float* Xs = (float*)sm;
        float* sx = (float*)(sm + 66560);
        float* tot = (float*)(sm + 67072);
#pragma unroll
        for (int mt = 0; mt < 2; mt++)
#pragma unroll
            for (int j = 0; j < 4; j++) {
                int row = m0w + mt * 16 + gr;
                int col = t0 + j * 8 + 2 * gc;
                *(float2*)&Xs[row * 130 + col] =
                    make_float2(fmaxf(acc[mt][j][0], 0.f), fmaxf(acc[mt][j][1], 0.f));
                *(float2*)&Xs[(row + 8) * 130 + col] =
                    make_float2(fmaxf(acc[mt][j][2], 0.f), fmaxf(acc[mt][j][3], 0.f));
            }
        __syncthreads();
        {
            int n = tid & 127, q = tid >> 7;
            float v[32];
            float a = 0.f;
#pragma unroll
            for (int i = 0; i < 16; i++) {
                float2 p = *(float2*)&Xs[n * 130 + q * 32 + 2 * i];
                a += p.x;
                v[2 * i] = a;
                a += p.y;
                v[2 * i + 1] = a;
            }
            tot[n * 4 + q] = a;
            __syncthreads();
            float off = 0.f;
#pragma unroll
            for (int qq = 0; qq < 3; qq++)
                if (qq < q) off += tot[n * 4 + qq];
#pragma unroll
            for (int p = 0; p < 16; p++) {
                float x0 = v[2 * p] + off, x1 = v[2 * p + 1] + off;
                *(float2*)&Xs[n * 130 + q * 32 + 2 * p] = make_float2(x0, x1);
                __half2 hp = __floats2half2_rn(x0, x1);
                float r0 = x0 - __half2float(__low2half(hp));
                float r1 = x1 - __half2float(__high2half(hp));
                __half2 lp = __floats2half2_rn(r0, r1);
                int wc = q * 16 + p;
                *(u32*)(sm + XBH + n * (PA2 * 4) + wc * 4) = *(u32*)&hp;
                *(u32*)(sm + XBL + n * (PA2 * 4) + wc * 4) = *(u32*)&lp;
            }
            if (q == 3) {
                float xf = v[31] + off;
                out[n0 + n] = xf;
                sx[n] = xf;
            }
        }
        __syncthreads();
        {
            int t = tid & 127, q = tid >> 7;
            float s = 0.f;
#pragma unroll 8
            for (int n2 = q * 32; n2 < q * 32 + 32; n2++)
                s = fmaf(Xs[n2 * 130 + t], sx[n2], s);
            tot[t * 4 + q] = s;
        }
        __syncthreads();
        if (tid < 128)
            g_part2[blockIdx.x * 128 + tid] =
                (tot[tid * 4] + tot[tid * 4 + 1]) + (tot[tid * 4 + 2] + tot[tid * 4 + 3]);
        __syncthreads();
    }

    // ======================= PHASE B =======================
    {
        int m0w = (wid & 7) * 32;
        int nb = (wid >> 3) * 64;

        float acc[2][8][4];
#pragma unroll
        for (int i = 0; i < 2; i++)
#pragma unroll
            for (int j = 0; j < 8; j++)
#pragma unroll
                for (int q = 0; q < 4; q++) acc[i][j][q] = 0.f;

#pragma unroll
        for (int ks = 0; ks < 8; ks++) {
            u32 ah[2][4];
#pragma unroll
            for (int mt = 0; mt < 2; mt++) {
                int aw = (m0w + mt * 16 + r8 + (sub & 1) * 8) * PA2 + (sub >> 1) * 4 + ks * 8;
                LDSM_X4(ah[mt], smb + SCV + aw * 4);
            }
#pragma unroll
            for (int g = 0; g < 4; g++) {
                u32 bh[4], bl[4];
                int bw = (nb + g * 16 + r8 + (sub >> 1) * 8) * PA2 + (sub & 1) * 4 + ks * 8;
                LDSM_X4(bh, smb + XBH + bw * 4);
                LDSM_X4(bl, smb + XBL + bw * 4);
                mma16816(acc[0][2 * g], ah[0], bh[0], bh[1]);
                mma16816(acc[1][2 * g], ah[1], bh[0], bh[1]);
                mma16816(acc[0][2 * g + 1], ah[0], bh[2], bh[3]);
                mma16816(acc[1][2 * g + 1], ah[1], bh[2], bh[3]);
                mma16816(acc[0][2 * g], ah[0], bl[0], bl[1]);
                mma16816(acc[1][2 * g], ah[1], bl[0], bl[1]);
                mma16816(acc[0][2 * g + 1], ah[0], bl[2], bl[3]);
                mma16816(acc[1][2 * g + 1], ah[1], bl[2], bl[3]);
            }
        }

        float* rho = out + 2 * N + D;
#pragma unroll
        for (int mt = 0; mt < 2; mt++)
#pragma unroll
            for (int j = 0; j < 8; j++) {
                int d = m0w + mt * 16 + gr;
                int col = n0 + nb + j * 8 + 2 * gc;
                *(float2*)&rho[(size_t)d * N + col] = make_float2(acc[mt][j][0], acc[mt][j][1]);
                *(float2*)&rho[(size_t)(d + 8) * N + col] =
                    make_float2(acc[mt][j][2], acc[mt][j][3]);
            }
    }
}

// ---------------- K3: a*[d] -> layernorm -> g_lnA ----------------------------
__global__ __launch_bounds__(1024) void k_astar_ln() {
    __shared__ float p1[1024];
    __shared__ float gg[T];
    __shared__ float p2[1024];
    __shared__ float red[256];
    int tid = threadIdx.x;
    {
        int t = tid & 127, q = tid >> 7;
        float s = 0.f;
#pragma unroll
        for (int b = q * 16; b < q * 16 + 16; b++) s += g_part2[b * 128 + t];
        p1[q * 128 + t] = s;
    }
    __syncthreads();
    if (tid < T) {
        float s = 0.f;
#pragma unroll
        for (int q = 0; q < 8; q++) s += p1[q * 128 + tid];
        float c = exp2f((float)(T - 1 - tid) * LOG2_097);
        gg[tid] = (tid < T - 1) ? c * s : 0.f;
    }
    __syncthreads();
    {
        int d = tid & 255, q = tid >> 8;
        float a = 0.f;
#pragma unroll
        for (int i = 0; i < 32; i++) {
            int s = q * 32 + i;
            a = fmaf(gg[s], g_V[s * D + d], a);
        }
        p2[q * 256 + d] = a;
    }
    __syncthreads();
    float a = 0.f;
    if (tid < 256) {
        a = (p2[tid] + p2[256 + tid]) + (p2[512 + tid] + p2[768 + tid]);
        red[tid] = a;
    }
    __syncthreads();
    for (int off = 128; off > 0; off >>= 1) {
        if (tid < off) red[tid] += red[tid + off];
        __syncthreads();
    }
    float m = red[0] * (1.f / D);
    __syncthreads();
    float ctr = a - m;
    if (tid < 256) red[tid] = ctr * ctr;
    __syncthreads();
    for (int off = 128; off > 0; off >>= 1) {
        if (tid < off) red[tid] += red[tid + off];
        __syncthreads();
    }
    if (tid < 256) {
        float sd = sqrtf(red[0] / (float)(D - 1));
        g_lnA[tid] = ctr / (sd + 1e-6f);
    }
}

// ---------------- K4: y = relu(Dyh.lnA)*relu(x_f); fp16 Dy, 8 rows/warp ------
__global__ __launch_bounds__(256) void k_y(float* __restrict__ out) {
    __shared__ float sa[D];
    int tid = threadIdx.x, lane = tid & 31, wid = tid >> 5;
    sa[tid] = g_lnA[tid];
    __syncthreads();
    float sreg[8];
#pragma unroll
    for (int j = 0; j < 8; j++) sreg[j] = sa[lane * 8 + j];
    int nbase = blockIdx.x * 64 + wid * 8;
    uint4 hv[8];
#pragma unroll
    for (int r = 0; r < 8; r++)
        hv[r] = *(const uint4*)&g_Dyh[(size_t)(nbase + r) * D + lane * 8];
#pragma unroll
    for (int r = 0; r < 8; r++) {
        __half2* hp = (__half2*)&hv[r];
        float s = 0.f;
#pragma unroll
        for (int q = 0; q < 4; q++) {
            float2 f = __half22float2(hp[q]);
            s = fmaf(f.x, sreg[2 * q], s);
            s = fmaf(f.y, sreg[2 * q + 1], s);
        }
#pragma unroll
        for (int off = 16; off > 0; off >>= 1) s += __shfl_down_sync(0xffffffffu, s, off);
        if (lane == 0) {
            float y = fmaxf(s, 0.f) * fmaxf(out[nbase + r], 0.f);
            out[N + nbase + r] = y;
            g_yh[nbase + r] = __float2half_rn(y);
        }
    }
}

// ---------------- K5: u[d] = Eh[d,:].yh (fp16, MLP 16) -----------------------
__global__ __launch_bounds__(256) void k_u() {
    __shared__ float red[256];
    int d = blockIdx.x, tid = threadIdx.x;
    const uint4* e = (const uint4*)&g_Eh[(size_t)d * N];
    const uint4* yv = (const uint4*)g_yh;
    float s = 0.f;
#pragma unroll
    for (int i = 0; i < 8; i++) {
        uint4 he = e[tid + 256 * i];
        uint4 hy = yv[tid + 256 * i];
        __half2* pe = (__half2*)&he;
        __half2* py = (__half2*)&hy;
#pragma unroll
        for (int q = 0; q < 4; q++) {
            float2 fe = __half22float2(pe[q]);
            float2 fy = __half22float2(py[q]);
            s = fmaf(fe.x, fy.x, s);
            s = fmaf(fe.y, fy.y, s);
        }
    }
    red[tid] = s;
    __syncthreads();
    for (int off = 128; off > 0; off >>= 1) {
        if (tid < off) red[tid] += red[tid + off];
        __syncthreads();
    }
    if (tid == 0) g_u[d] = red[0];
}

// ---------------- K6: v* = layernorm(u) -> out[2N:2N+D) ---------------------
__global__ void k_vstar(float* __restrict__ out) {
    __shared__ float red[256];
    int tid = threadIdx.x;
    float a = g_u[tid];
    red[tid] = a;
    __syncthreads();
    for (int off = 128; off > 0; off >>= 1) {
        if (tid < off) red[tid] += red[tid + off];
        __syncthreads();
    }
    float m = red[0] * (1.f / D);
    __syncthreads();
    float c = a - m;
    red[tid] = c * c;
    __syncthreads();
    for (int off = 128; off > 0; off >>= 1) {
        if (tid < off) red[tid] += red[tid + off];
        __syncthreads();
    }
    float sd = sqrtf(red[0] / (float)(D - 1));
    out[2 * N + tid] = c / (sd + 1e-6f);
}

// ---------------------------------------------------------------------------
extern "C" void kernel_launch(void* const* d_in, const int* in_sizes, int n_in,
                              void* d_out, int out_size) {
    const float* E    = (const float*)d_in[0];
    const float* Dx   = (const float*)d_in[1];
    const float* Dy   = (const float*)d_in[2];
    const float* temb = (const float*)d_in[3];
    const int*   toks = (const int*)d_in[4];
    float* out = (float*)d_out;

    const int SM12 = 208896;
    static int inited = 0;
    static cudaStream_t s2;
    static cudaEvent_t ev0, evc;
    if (!inited) {
        cudaFuncSetAttribute(k_gemm12, cudaFuncAttributeMaxDynamicSharedMemorySize, SM12);
        cudaStreamCreateWithFlags(&s2, cudaStreamNonBlocking);
        cudaEventCreateWithFlags(&ev0, cudaEventDisableTiming);
        cudaEventCreateWithFlags(&evc, cudaEventDisableTiming);
        inited = 1;
    }

    // legal capture fork: record on captured stream 0 FIRST, then s2 waits on it
    cudaEventRecord(ev0, 0);
    cudaStreamWaitEvent(s2, ev0, 0);
    k_cvt<<<4096, 256, 0, s2>>>(Dy, E);  // overlaps with prep + gemm12
    cudaEventRecord(evc, s2);

    k_prep<<<T, 256>>>(temb, toks);
    k_gemm12<<<N / 128, 512, SM12>>>(Dx, out);
    k_astar_ln<<<1, 1024>>>();

    cudaStreamWaitEvent(0, evc, 0);  // join: y needs g_Dyh
    k_y<<<N / 64, 256>>>(out);
    k_u<<<D, 256>>>();
    k_vstar<<<1, D>>>(out);
}

// round 14
// speedup vs baseline: 1.0835x; 1.0835x over previous
#include <cuda_runtime.h>
#include <cuda_fp16.h>
#include <math.h>

#define N 16384
#define D 256
#define T 128
#define LOG2_097 (-0.04394334758759706f)

typedef unsigned int u32;
typedef unsigned long long u64;

// ---------------- scratch ---------------------------------------------------
__device__ float  g_V[T * D];      // gathered token embeddings fp32 [t][d]
__device__ __half g_Vh[T * D];     // V hi fp16 [t][k]
__device__ __half g_Vl[T * D];     // V lo (residual) fp16 [t][k]
__device__ __half g_cV[D * T];     // (0.97^(T-s)*V[s][d]) single fp16 [d][s]
__device__ float  g_part2[128 * T];
__device__ float  g_lnA[D];
__device__ float  g_u[D];

// ---------------- helpers ----------------------------------------------------
__device__ __forceinline__ u32 s2u(const void* p) {
    u32 a;
    asm("{ .reg .u64 t; cvta.to.shared.u64 t, %1; cvt.u32.u64 %0, t; }" : "=r"(a) : "l"(p));
    return a;
}

#define LDSM_X4(r, addr)                                                        \
    asm volatile(                                                               \
        "ldmatrix.sync.aligned.m8n8.x4.shared.b16 {%0,%1,%2,%3}, [%4];"         \
        : "=r"((r)[0]), "=r"((r)[1]), "=r"((r)[2]), "=r"((r)[3])                \
        : "r"(addr))

__device__ __forceinline__ void mma16816(float* c, const u32* a, u32 b0, u32 b1) {
    asm volatile(
        "mma.sync.aligned.m16n8k16.row.col.f32.f16.f16.f32 "
        "{%0,%1,%2,%3}, {%4,%5,%6,%7}, {%8,%9}, {%0,%1,%2,%3};"
        : "+f"(c[0]), "+f"(c[1]), "+f"(c[2]), "+f"(c[3])
        : "r"(a[0]), "r"(a[1]), "r"(a[2]), "r"(a[3]), "r"(b0), "r"(b1));
}

// float4 -> 4 packed fp16 (u64)
__device__ __forceinline__ u64 to_h4(float4 v) {
    __half2 a = __floats2half2_rn(v.x, v.y);
    __half2 b = __floats2half2_rn(v.z, v.w);
    u32 ua = *(u32*)&a, ub = *(u32*)&b;
    return ((u64)ub << 32) | ua;
}

// ---------------- K0: L2 prefetch of Dy & E (hint only, no writes) -----------
__global__ __launch_bounds__(256) void k_warm(const float* __restrict__ Dy,
                                              const float* __restrict__ E) {
    size_t i = ((size_t)blockIdx.x * 256 + threadIdx.x) * 32;  // one 128B line
    asm volatile("prefetch.global.L2 [%0];" ::"l"(&Dy[i]));
    asm volatile("prefetch.global.L2 [%0];" ::"l"(&E[i]));
}

// ---------------- K1: gather + V splits + cV (fused prep) --------------------
__global__ __launch_bounds__(256) void k_prep(const float* __restrict__ temb,
                                              const int* __restrict__ toks) {
    int t = blockIdx.x, d = threadIdx.x;
    float v = temb[(size_t)toks[t] * D + d];
    g_V[t * D + d] = v;
    __half hv = __float2half_rn(v);
    g_Vh[t * D + d] = hv;
    g_Vl[t * D + d] = __float2half_rn(v - __half2float(hv));
    float c = exp2f((float)(T - t) * LOG2_097);
    g_cV[d * T + t] = __float2half_rn(c * v);
}

// ---------------- K2: FUSED GEMM1 + GEMM2 ------------------------------------
#define PA1 36
#define PA2 68
__global__ __launch_bounds__(512) void k_gemm12(const float* __restrict__ Dx,
                                                float* __restrict__ out) {
    extern __shared__ char sm[];
    const int S_A = 0, S_BH = 18432, S_BL = 36864;
    const int XBH = 69632, XBL = 104448, SCV = 139264;  // ends 208896
    int tid = threadIdx.x;
    int lane = tid & 31, wid = tid >> 5;
    int gr = lane >> 2, gc = lane & 3;
    int r8 = lane & 7, sub = lane >> 3;
    int n0 = blockIdx.x * 128;
    u32 smb = s2u(sm);

#pragma unroll
    for (int r = 0; r < 8; r++) {
        int gi = tid + 512 * r;
        int row = gi >> 4, j4 = gi & 15;
        *(uint4*)(sm + SCV + row * (PA2 * 4) + j4 * 16) = ((const uint4*)g_cV)[row * 16 + j4];
    }

    // ======================= PHASE A =======================
    {
        int m0w = (wid & 3) * 32;
        int t0 = (wid >> 2) * 32;

        float acc[2][4][4];
#pragma unroll
        for (int i = 0; i < 2; i++)
#pragma unroll
            for (int j = 0; j < 4; j++)
#pragma unroll
                for (int q = 0; q < 4; q++) acc[i][j][q] = 0.f;

        float4 pa[4];
        uint4 pbh[2], pbl[2];
#pragma unroll
        for (int r = 0; r < 4; r++) {
            int gi = tid + 512 * r;
            int row = gi >> 4, f4 = gi & 15;
            pa[r] = *(const float4*)&Dx[(size_t)(n0 + row) * D + f4 * 4];
        }
#pragma unroll
        for (int r = 0; r < 2; r++) {
            int gi = tid + 512 * r;
            int row = gi >> 3, j4 = gi & 7;
            pbh[r] = ((const uint4*)g_Vh)[row * 32 + j4];
            pbl[r] = ((const uint4*)g_Vl)[row * 32 + j4];
        }

        for (int c = 0; c < 4; c++) {
#pragma unroll
            for (int r = 0; r < 4; r++) {
                int gi = tid + 512 * r;
                int row = gi >> 4, f4 = gi & 15;
                *(u64*)(sm + S_A + row * (PA1 * 4) + f4 * 8) = to_h4(pa[r]);
            }
#pragma unroll
            for (int r = 0; r < 2; r++) {
                int gi = tid + 512 * r;
                int row = gi >> 3, j4 = gi & 7;
                *(uint4*)(sm + S_BH + row * (PA1 * 4) + j4 * 16) = pbh[r];
                *(uint4*)(sm + S_BL + row * (PA1 * 4) + j4 * 16) = pbl[r];
            }
            __syncthreads();
            if (c < 3) {
#pragma unroll
                for (int r = 0; r < 4; r++) {
                    int gi = tid + 512 * r;
                    int row = gi >> 4, f4 = gi & 15;
                    pa[r] = *(const float4*)&Dx[(size_t)(n0 + row) * D + (c + 1) * 64 + f4 * 4];
                }
#pragma unroll
                for (int r = 0; r < 2; r++) {
                    int gi = tid + 512 * r;
                    int row = gi >> 3, j4 = gi & 7;
                    pbh[r] = ((const uint4*)g_Vh)[row * 32 + (c + 1) * 8 + j4];
                    pbl[r] = ((const uint4*)g_Vl)[row * 32 + (c + 1) * 8 + j4];
                }
            }
#pragma unroll
            for (int ks = 0; ks < 4; ks++) {
                u32 ah[2][4], bh[2][4], bl[2][4];
#pragma unroll
                for (int mt = 0; mt < 2; mt++) {
                    int aw = (m0w + mt * 16 + r8 + (sub & 1) * 8) * PA1 + (sub >> 1) * 4 + ks * 8;
                    LDSM_X4(ah[mt], smb + S_A + aw * 4);
                }
#pragma unroll
                for (int g = 0; g < 2; g++) {
                    int bw = (t0 + g * 16 + r8 + (sub >> 1) * 8) * PA1 + (sub & 1) * 4 + ks * 8;
                    LDSM_X4(bh[g], smb + S_BH + bw * 4);
                    LDSM_X4(bl[g], smb + S_BL + bw * 4);
                }
#pragma unroll
                for (int g = 0; g < 2; g++)
#pragma unroll
                    for (int mt = 0; mt < 2; mt++) {
                        mma16816(acc[mt][2 * g], ah[mt], bh[g][0], bh[g][1]);
                        mma16816(acc[mt][2 * g + 1], ah[mt], bh[g][2], bh[g][3]);
                    }
#pragma unroll
                for (int g = 0; g < 2; g++)
#pragma unroll
                    for (int mt = 0; mt < 2; mt++) {
                        mma16816(acc[mt][2 * g], ah[mt], bl[g][0], bl[g][1]);
                        mma16816(acc[mt][2 * g + 1], ah[mt], bl[g][2], bl[g][3]);
                    }
            }
            __syncthreads();
        }

        float* Xs = (float*)sm;
        float* sx = (float*)(sm + 66560);
        float* tot = (float*)(sm + 67072);
#pragma unroll
        for (int mt = 0; mt < 2; mt++)
#pragma unroll
            for (int j = 0; j < 4; j++) {
                int row = m0w + mt * 16 + gr;
                int col = t0 + j * 8 + 2 * gc;
                *(float2*)&Xs[row * 130 + col] =
                    make_float2(fmaxf(acc[mt][j][0], 0.f), fmaxf(acc[mt][j][1], 0.f));
                *(float2*)&Xs[(row + 8) * 130 + col] =
                    make_float2(fmaxf(acc[mt][j][2], 0.f), fmaxf(acc[mt][j][3], 0.f));
            }
        __syncthreads();
        {
            int n = tid & 127, q = tid >> 7;
            float v[32];
            float a = 0.f;
#pragma unroll
            for (int i = 0; i < 16; i++) {
                float2 p = *(float2*)&Xs[n * 130 + q * 32 + 2 * i];
                a += p.x;
                v[2 * i] = a;
                a += p.y;
                v[2 * i + 1] = a;
            }
            tot[n * 4 + q] = a;
            __syncthreads();
            float off = 0.f;
#pragma unroll
            for (int qq = 0; qq < 3; qq++)
                if (qq < q) off += tot[n * 4 + qq];
#pragma unroll
            for (int p = 0; p < 16; p++) {
                float x0 = v[2 * p] + off, x1 = v[2 * p + 1] + off;
                *(float2*)&Xs[n * 130 + q * 32 + 2 * p] = make_float2(x0, x1);
                __half2 hp = __floats2half2_rn(x0, x1);
                float r0 = x0 - __half2float(__low2half(hp));
                float r1 = x1 - __half2float(__high2half(hp));
                __half2 lp = __floats2half2_rn(r0, r1);
                int wc = q * 16 + p;
                *(u32*)(sm + XBH + n * (PA2 * 4) + wc * 4) = *(u32*)&hp;
                *(u32*)(sm + XBL + n * (PA2 * 4) + wc * 4) = *(u32*)&lp;
            }
            if (q == 3) {
                float xf = v[31] + off;
                out[n0 + n] = xf;
                sx[n] = xf;
            }
        }
        __syncthreads();
        {
            int t = tid & 127, q = tid >> 7;
            float s = 0.f;
#pragma unroll 8
            for (int n2 = q * 32; n2 < q * 32 + 32; n2++)
                s = fmaf(Xs[n2 * 130 + t], sx[n2], s);
            tot[t * 4 + q] = s;
        }
        __syncthreads();
        if (tid < 128)
            g_part2[blockIdx.x * 128 + tid] =
                (tot[tid * 4] + tot[tid * 4 + 1]) + (tot[tid * 4 + 2] + tot[tid * 4 + 3]);
        __syncthreads();
    }

    // ======================= PHASE B =======================
    {
        int m0w = (wid & 7) * 32;
        int nb = (wid >> 3) * 64;

        float acc[2][8][4];
#pragma unroll
        for (int i = 0; i < 2; i++)
#pragma unroll
            for (int j = 0; j < 8; j++)
#pragma unroll
                for (int q = 0; q < 4; q++) acc[i][j][q] = 0.f;

#pragma unroll
        for (int ks = 0; ks < 8; ks++) {
            u32 ah[2][4];
#pragma unroll
            for (int mt = 0; mt < 2; mt++) {
                int aw = (m0w + mt * 16 + r8 + (sub & 1) * 8) * PA2 + (sub >> 1) * 4 + ks * 8;
                LDSM_X4(ah[mt], smb + SCV + aw * 4);
            }
#pragma unroll
            for (int g = 0; g < 4; g++) {
                u32 bh[4], bl[4];
                int bw = (nb + g * 16 + r8 + (sub >> 1) * 8) * PA2 + (sub & 1) * 4 + ks * 8;
                LDSM_X4(bh, smb + XBH + bw * 4);
                LDSM_X4(bl, smb + XBL + bw * 4);
                mma16816(acc[0][2 * g], ah[0], bh[0], bh[1]);
                mma16816(acc[1][2 * g], ah[1], bh[0], bh[1]);
                mma16816(acc[0][2 * g + 1], ah[0], bh[2], bh[3]);
                mma16816(acc[1][2 * g + 1], ah[1], bh[2], bh[3]);
                mma16816(acc[0][2 * g], ah[0], bl[0], bl[1]);
                mma16816(acc[1][2 * g], ah[1], bl[0], bl[1]);
                mma16816(acc[0][2 * g + 1], ah[0], bl[2], bl[3]);
                mma16816(acc[1][2 * g + 1], ah[1], bl[2], bl[3]);
            }
        }

        float* rho = out + 2 * N + D;
#pragma unroll
        for (int mt = 0; mt < 2; mt++)
#pragma unroll
            for (int j = 0; j < 8; j++) {
                int d = m0w + mt * 16 + gr;
                int col = n0 + nb + j * 8 + 2 * gc;
                *(float2*)&rho[(size_t)d * N + col] = make_float2(acc[mt][j][0], acc[mt][j][1]);
                *(float2*)&rho[(size_t)(d + 8) * N + col] =
                    make_float2(acc[mt][j][2], acc[mt][j][3]);
            }
    }
}

// ---------------- K3: a*[d] -> layernorm -> g_lnA ----------------------------
__global__ __launch_bounds__(1024) void k_astar_ln() {
    __shared__ float p1[1024];
    __shared__ float gg[T];
    __shared__ float p2[1024];
    __shared__ float red[256];
    int tid = threadIdx.x;
    {
        int t = tid & 127, q = tid >> 7;
        float s = 0.f;
#pragma unroll
        for (int b = q * 16; b < q * 16 + 16; b++) s += g_part2[b * 128 + t];
        p1[q * 128 + t] = s;
    }
    __syncthreads();
    if (tid < T) {
        float s = 0.f;
#pragma unroll
        for (int q = 0; q < 8; q++) s += p1[q * 128 + tid];
        float c = exp2f((float)(T - 1 - tid) * LOG2_097);
        gg[tid] = (tid < T - 1) ? c * s : 0.f;
    }
    __syncthreads();
    {
        int d = tid & 255, q = tid >> 8;
        float a = 0.f;
#pragma unroll
        for (int i = 0; i < 32; i++) {
            int s = q * 32 + i;
            a = fmaf(gg[s], g_V[s * D + d], a);
        }
        p2[q * 256 + d] = a;
    }
    __syncthreads();
    float a = 0.f;
    if (tid < 256) {
        a = (p2[tid] + p2[256 + tid]) + (p2[512 + tid] + p2[768 + tid]);
        red[tid] = a;
    }
    __syncthreads();
    for (int off = 128; off > 0; off >>= 1) {
        if (tid < off) red[tid] += red[tid + off];
        __syncthreads();
    }
    float m = red[0] * (1.f / D);
    __syncthreads();
    float ctr = a - m;
    if (tid < 256) red[tid] = ctr * ctr;
    __syncthreads();
    for (int off = 128; off > 0; off >>= 1) {
        if (tid < off) red[tid] += red[tid + off];
        __syncthreads();
    }
    if (tid < 256) {
        float sd = sqrtf(red[0] / (float)(D - 1));
        g_lnA[tid] = ctr / (sd + 1e-6f);
    }
}

// ---------------- K4: y = relu(Dy.lnA)*relu(x_f); 4 rows/warp, MLP 8 ---------
__global__ __launch_bounds__(256) void k_y(const float* __restrict__ Dy,
                                           float* __restrict__ out) {
    __shared__ float sa[D];
    int tid = threadIdx.x, lane = tid & 31, wid = tid >> 5;
    sa[tid] = g_lnA[tid];
    __syncthreads();
    float sreg[8];
#pragma unroll
    for (int j = 0; j < 8; j++) sreg[j] = sa[lane * 8 + j];
    int nbase = blockIdx.x * 32 + wid * 4;
    float4 v0[4], v1[4];
#pragma unroll
    for (int r = 0; r < 4; r++) {
        const float* row = &Dy[(size_t)(nbase + r) * D + lane * 8];
        v0[r] = *(const float4*)row;
        v1[r] = *(const float4*)(row + 4);
    }
#pragma unroll
    for (int r = 0; r < 4; r++) {
        float s = 0.f;
        s = fmaf(v0[r].x, sreg[0], s);
        s = fmaf(v0[r].y, sreg[1], s);
        s = fmaf(v0[r].z, sreg[2], s);
        s = fmaf(v0[r].w, sreg[3], s);
        s = fmaf(v1[r].x, sreg[4], s);
        s = fmaf(v1[r].y, sreg[5], s);
        s = fmaf(v1[r].z, sreg[6], s);
        s = fmaf(v1[r].w, sreg[7], s);
#pragma unroll
        for (int off = 16; off > 0; off >>= 1) s += __shfl_down_sync(0xffffffffu, s, off);
        if (lane == 0)
            out[N + nbase + r] = fmaxf(s, 0.f) * fmaxf(out[nbase + r], 0.f);
    }
}

// ---------------- K5: u[d] = E[d,:].y (unroll 8, MLP 16) ---------------------
__global__ __launch_bounds__(256) void k_u(const float* __restrict__ E,
                                           const float* __restrict__ out) {
    __shared__ float red[256];
    int d = blockIdx.x, tid = threadIdx.x;
    const float4* e = (const float4*)&E[(size_t)d * N];
    const float4* y = (const float4*)&out[N];
    float s = 0.f;
#pragma unroll 8
    for (int r = 0; r < 16; r++) {
        float4 a = e[tid + 256 * r];
        float4 b = y[tid + 256 * r];
        s = fmaf(a.x, b.x, s);
        s = fmaf(a.y, b.y, s);
        s = fmaf(a.z, b.z, s);
        s = fmaf(a.w, b.w, s);
    }
    red[tid] = s;
    __syncthreads();
    for (int off = 128; off > 0; off >>= 1) {
        if (tid < off) red[tid] += red[tid + off];
        __syncthreads();
    }
    if (tid == 0) g_u[d] = red[0];
}

// ---------------- K6: v* = layernorm(u) -> out[2N:2N+D) ---------------------
__global__ void k_vstar(float* __restrict__ out) {
    __shared__ float red[256];
    int tid = threadIdx.x;
    float a = g_u[tid];
    red[tid] = a;
    __syncthreads();
    for (int off = 128; off > 0; off >>= 1) {
        if (tid < off) red[tid] += red[tid + off];
        __syncthreads();
    }
    float m = red[0] * (1.f / D);
    __syncthreads();
    float c = a - m;
    red[tid] = c * c;
    __syncthreads();
    for (int off = 128; off > 0; off >>= 1) {
        if (tid < off) red[tid] += red[tid + off];
        __syncthreads();
    }
    float sd = sqrtf(red[0] / (float)(D - 1));
    out[2 * N + tid] = c / (sd + 1e-6f);
}

// ---------------------------------------------------------------------------
extern "C" void kernel_launch(void* const* d_in, const int* in_sizes, int n_in,
                              void* d_out, int out_size) {
    const float* E    = (const float*)d_in[0];
    const float* Dx   = (const float*)d_in[1];
    const float* Dy   = (const float*)d_in[2];
    const float* temb = (const float*)d_in[3];
    const int*   toks = (const int*)d_in[4];
    float* out = (float*)d_out;

    const int SM12 = 208896;
    static int inited = 0;
    static cudaStream_t s2;
    static cudaEvent_t ev0, evw;
    if (!inited) {
        cudaFuncSetAttribute(k_gemm12, cudaFuncAttributeMaxDynamicSharedMemorySize, SM12);
        cudaStreamCreateWithFlags(&s2, cudaStreamNonBlocking);
        cudaEventCreateWithFlags(&ev0, cudaEventDisableTiming);
        cudaEventCreateWithFlags(&evw, cudaEventDisableTiming);
        inited = 1;
    }

    // fork: L2 prefetch of Dy & E overlaps with prep + gemm12 (hint only)
    cudaEventRecord(ev0, 0);
    cudaStreamWaitEvent(s2, ev0, 0);
    k_warm<<<512, 256, 0, s2>>>(Dy, E);  // 131072 threads, 1 line each per array
    cudaEventRecord(evw, s2);

    k_prep<<<T, 256>>>(temb, toks);
    k_gemm12<<<N / 128, 512, SM12>>>(Dx, out);
    k_astar_ln<<<1, 1024>>>();

    cudaStreamWaitEvent(0, evw, 0);  // join (prefetch long done by now)
    k_y<<<N / 32, 256>>>(Dy, out);
    k_u<<<D, 256>>>(E, out);
    k_vstar<<<1, D>>>(out);
}

// round 15
// speedup vs baseline: 1.1354x; 1.0480x over previous
#include <cuda_runtime.h>
#include <cuda_fp16.h>
#include <math.h>

#define N 16384
#define D 256
#define T 128
#define LOG2_097 (-0.04394334758759706f)

typedef unsigned int u32;
typedef unsigned long long u64;

// ---------------- scratch ---------------------------------------------------
__device__ float  g_V[T * D];      // gathered token embeddings fp32 [t][d]
__device__ __half g_Vh[T * D];     // V hi fp16 [t][k]
__device__ __half g_Vl[T * D];     // V lo (residual) fp16 [t][k]
__device__ __half g_cV[D * T];     // (0.97^(T-s)*V[s][d]) single fp16 [d][s]
__device__ float  g_part2[128 * T];
__device__ float  g_lnA[D];
__device__ float  g_u[D];
__device__ int    g_ctr1 = 0;      // last-block counters (self-resetting)
__device__ int    g_ctr2 = 0;

// ---------------- helpers ----------------------------------------------------
__device__ __forceinline__ u32 s2u(const void* p) {
    u32 a;
    asm("{ .reg .u64 t; cvta.to.shared.u64 t, %1; cvt.u32.u64 %0, t; }" : "=r"(a) : "l"(p));
    return a;
}

#define LDSM_X4(r, addr)                                                        \
    asm volatile(                                                               \
        "ldmatrix.sync.aligned.m8n8.x4.shared.b16 {%0,%1,%2,%3}, [%4];"         \
        : "=r"((r)[0]), "=r"((r)[1]), "=r"((r)[2]), "=r"((r)[3])                \
        : "r"(addr))

__device__ __forceinline__ void mma16816(float* c, const u32* a, u32 b0, u32 b1) {
    asm volatile(
        "mma.sync.aligned.m16n8k16.row.col.f32.f16.f16.f32 "
        "{%0,%1,%2,%3}, {%4,%5,%6,%7}, {%8,%9}, {%0,%1,%2,%3};"
        : "+f"(c[0]), "+f"(c[1]), "+f"(c[2]), "+f"(c[3])
        : "r"(a[0]), "r"(a[1]), "r"(a[2]), "r"(a[3]), "r"(b0), "r"(b1));
}

// float4 -> 4 packed fp16 (u64)
__device__ __forceinline__ u64 to_h4(float4 v) {
    __half2 a = __floats2half2_rn(v.x, v.y);
    __half2 b = __floats2half2_rn(v.z, v.w);
    u32 ua = *(u32*)&a, ub = *(u32*)&b;
    return ((u64)ub << 32) | ua;
}

// ---------------- K1: gather + V splits + cV (fused prep) --------------------
__global__ __launch_bounds__(256) void k_prep(const float* __restrict__ temb,
                                              const int* __restrict__ toks) {
    int t = blockIdx.x, d = threadIdx.x;
    float v = temb[(size_t)toks[t] * D + d];
    g_V[t * D + d] = v;
    __half hv = __float2half_rn(v);
    g_Vh[t * D + d] = hv;
    g_Vl[t * D + d] = __float2half_rn(v - __half2float(hv));
    float c = exp2f((float)(T - t) * LOG2_097);
    g_cV[d * T + t] = __float2half_rn(c * v);
}

// ---------------- K2: FUSED GEMM1 + GEMM2 + (last block) ASTAR+LN ------------
#define PA1 36
#define PA2 68
__global__ __launch_bounds__(512) void k_gemm12(const float* __restrict__ Dx,
                                                float* __restrict__ out) {
    extern __shared__ char sm[];
    __shared__ int sflag;
    const int S_A = 0, S_BH = 18432, S_BL = 36864;
    const int XBH = 69632, XBL = 104448, SCV = 139264;  // ends 208896
    int tid = threadIdx.x;
    int lane = tid & 31, wid = tid >> 5;
    int gr = lane >> 2, gc = lane & 3;
    int r8 = lane & 7, sub = lane >> 3;
    int n0 = blockIdx.x * 128;
    u32 smb = s2u(sm);

#pragma unroll
    for (int r = 0; r < 8; r++) {
        int gi = tid + 512 * r;
        int row = gi >> 4, j4 = gi & 15;
        *(uint4*)(sm + SCV + row * (PA2 * 4) + j4 * 16) = ((const uint4*)g_cV)[row * 16 + j4];
    }

    // ======================= PHASE A =======================
    {
        int m0w = (wid & 3) * 32;
        int t0 = (wid >> 2) * 32;

        float acc[2][4][4];
#pragma unroll
        for (int i = 0; i < 2; i++)
#pragma unroll
            for (int j = 0; j < 4; j++)
#pragma unroll
                for (int q = 0; q < 4; q++) acc[i][j][q] = 0.f;

        float4 pa[4];
        uint4 pbh[2], pbl[2];
#pragma unroll
        for (int r = 0; r < 4; r++) {
            int gi = tid + 512 * r;
            int row = gi >> 4, f4 = gi & 15;
            pa[r] = *(const float4*)&Dx[(size_t)(n0 + row) * D + f4 * 4];
        }
#pragma unroll
        for (int r = 0; r < 2; r++) {
            int gi = tid + 512 * r;
            int row = gi >> 3, j4 = gi & 7;
            pbh[r] = ((const uint4*)g_Vh)[row * 32 + j4];
            pbl[r] = ((const uint4*)g_Vl)[row * 32 + j4];
        }

        for (int c = 0; c < 4; c++) {
#pragma unroll
            for (int r = 0; r < 4; r++) {
                int gi = tid + 512 * r;
                int row = gi >> 4, f4 = gi & 15;
                *(u64*)(sm + S_A + row * (PA1 * 4) + f4 * 8) = to_h4(pa[r]);
            }
#pragma unroll
            for (int r = 0; r < 2; r++) {
                int gi = tid + 512 * r;
                int row = gi >> 3, j4 = gi & 7;
                *(uint4*)(sm + S_BH + row * (PA1 * 4) + j4 * 16) = pbh[r];
                *(uint4*)(sm + S_BL + row * (PA1 * 4) + j4 * 16) = pbl[r];
            }
            __syncthreads();
            if (c < 3) {
#pragma unroll
                for (int r = 0; r < 4; r++) {
                    int gi = tid + 512 * r;
                    int row = gi >> 4, f4 = gi & 15;
                    pa[r] = *(const float4*)&Dx[(size_t)(n0 + row) * D + (c + 1) * 64 + f4 * 4];
                }
#pragma unroll
                for (int r = 0; r < 2; r++) {
                    int gi = tid + 512 * r;
                    int row = gi >> 3, j4 = gi & 7;
                    pbh[r] = ((const uint4*)g_Vh)[row * 32 + (c + 1) * 8 + j4];
                    pbl[r] = ((const uint4*)g_Vl)[row * 32 + (c + 1) * 8 + j4];
                }
            }
#pragma unroll
            for (int ks = 0; ks < 4; ks++) {
                u32 ah[2][4], bh[2][4], bl[2][4];
#pragma unroll
                for (int mt = 0; mt < 2; mt++) {
                    int aw = (m0w + mt * 16 + r8 + (sub & 1) * 8) * PA1 + (sub >> 1) * 4 + ks * 8;
                    LDSM_X4(ah[mt], smb + S_A + aw * 4);
                }
#pragma unroll
                for (int g = 0; g < 2; g++) {
                    int bw = (t0 + g * 16 + r8 + (sub >> 1) * 8) * PA1 + (sub & 1) * 4 + ks * 8;
                    LDSM_X4(bh[g], smb + S_BH + bw * 4);
                    LDSM_X4(bl[g], smb + S_BL + bw * 4);
                }
#pragma unroll
                for (int g = 0; g < 2; g++)
#pragma unroll
                    for (int mt = 0; mt < 2; mt++) {
                        mma16816(acc[mt][2 * g], ah[mt], bh[g][0], bh[g][1]);
                        mma16816(acc[mt][2 * g + 1], ah[mt], bh[g][2], bh[g][3]);
                    }
#pragma unroll
                for (int g = 0; g < 2; g++)
#pragma unroll
                    for (int mt = 0; mt < 2; mt++) {
                        mma16816(acc[mt][2 * g], ah[mt], bl[g][0], bl[g][1]);
                        mma16816(acc[mt][2 * g + 1], ah[mt], bl[g][2], bl[g][3]);
                    }
            }
            __syncthreads();
        }

        float* Xs = (float*)sm;
        float* sx = (float*)(sm + 66560);
        float* tot = (float*)(sm + 67072);
#pragma unroll
        for (int mt = 0; mt < 2; mt++)
#pragma unroll
            for (int j = 0; j < 4; j++) {
                int row = m0w + mt * 16 + gr;
                int col = t0 + j * 8 + 2 * gc;
                *(float2*)&Xs[row * 130 + col] =
                    make_float2(fmaxf(acc[mt][j][0], 0.f), fmaxf(acc[mt][j][1], 0.f));
                *(float2*)&Xs[(row + 8) * 130 + col] =
                    make_float2(fmaxf(acc[mt][j][2], 0.f), fmaxf(acc[mt][j][3], 0.f));
            }
        __syncthreads();
        {
            int n = tid & 127, q = tid >> 7;
            float v[32];
            float a = 0.f;
#pragma unroll
            for (int i = 0; i < 16; i++) {
                float2 p = *(float2*)&Xs[n * 130 + q * 32 + 2 * i];
                a += p.x;
                v[2 * i] = a;
                a += p.y;
                v[2 * i + 1] = a;
            }
            tot[n * 4 + q] = a;
            __syncthreads();
            float off = 0.f;
#pragma unroll
            for (int qq = 0; qq < 3; qq++)
                if (qq < q) off += tot[n * 4 + qq];
#pragma unroll
            for (int p = 0; p < 16; p++) {
                float x0 = v[2 * p] + off, x1 = v[2 * p + 1] + off;
                *(float2*)&Xs[n * 130 + q * 32 + 2 * p] = make_float2(x0, x1);
                __half2 hp = __floats2half2_rn(x0, x1);
                float r0 = x0 - __half2float(__low2half(hp));
                float r1 = x1 - __half2float(__high2half(hp));
                __half2 lp = __floats2half2_rn(r0, r1);
                int wc = q * 16 + p;
                *(u32*)(sm + XBH + n * (PA2 * 4) + wc * 4) = *(u32*)&hp;
                *(u32*)(sm + XBL + n * (PA2 * 4) + wc * 4) = *(u32*)&lp;
            }
            if (q == 3) {
                float xf = v[31] + off;
                out[n0 + n] = xf;
                sx[n] = xf;
            }
        }
        __syncthreads();
        {
            int t = tid & 127, q = tid >> 7;
            float s = 0.f;
#pragma unroll 8
            for (int n2 = q * 32; n2 < q * 32 + 32; n2++)
                s = fmaf(Xs[n2 * 130 + t], sx[n2], s);
            tot[t * 4 + q] = s;
        }
        __syncthreads();
        if (tid < 128)
            g_part2[blockIdx.x * 128 + tid] =
                (tot[tid * 4] + tot[tid * 4 + 1]) + (tot[tid * 4 + 2] + tot[tid * 4 + 3]);
        __syncthreads();
    }

    // ---- last-block election: the 128th block computes astar + layernorm ----
    if (tid == 0) {
        __threadfence();
        sflag = (atomicAdd(&g_ctr1, 1) == 127);
    }
    __syncthreads();
    if (sflag) {
        // reuse dead phase-A smem region [0..5KB)
        float* p1 = (float*)sm;            // [4][128]
        float* gg = (float*)(sm + 2048);   // [128]
        float* p2 = (float*)(sm + 2560);   // [2][256]
        float* red = (float*)(sm + 4608);  // [256]
        {
            int t = tid & 127, q = tid >> 7;  // q in [0,4)
            float s = 0.f;
#pragma unroll 8
            for (int b = q * 32; b < q * 32 + 32; b++) s += g_part2[b * 128 + t];
            p1[q * 128 + t] = s;
        }
        __syncthreads();
        if (tid < T) {
            float s = (p1[tid] + p1[128 + tid]) + (p1[256 + tid] + p1[384 + tid]);
            float c = exp2f((float)(T - 1 - tid) * LOG2_097);
            gg[tid] = (tid < T - 1) ? c * s : 0.f;
        }
        __syncthreads();
        {
            int d = tid & 255, q = tid >> 8;  // q in [0,2)
            float a = 0.f;
#pragma unroll 8
            for (int i = 0; i < 64; i++) {
                int s = q * 64 + i;
                a = fmaf(gg[s], g_V[s * D + d], a);
            }
            p2[q * 256 + d] = a;
        }
        __syncthreads();
        float a = 0.f;
        if (tid < 256) {
            a = p2[tid] + p2[256 + tid];
            red[tid] = a;
        }
        __syncthreads();
        for (int off = 128; off > 0; off >>= 1) {
            if (tid < off) red[tid] += red[tid + off];
            __syncthreads();
        }
        float m = red[0] * (1.f / D);
        __syncthreads();
        float ctr = a - m;
        if (tid < 256) red[tid] = ctr * ctr;
        __syncthreads();
        for (int off = 128; off > 0; off >>= 1) {
            if (tid < off) red[tid] += red[tid + off];
            __syncthreads();
        }
        if (tid < 256) {
            float sd = sqrtf(red[0] / (float)(D - 1));
            g_lnA[tid] = ctr / (sd + 1e-6f);
        }
        if (tid == 0) g_ctr1 = 0;  // reset for next graph replay
        __syncthreads();
    }

    // ======================= PHASE B =======================
    {
        int m0w = (wid & 7) * 32;
        int nb = (wid >> 3) * 64;

        float acc[2][8][4];
#pragma unroll
        for (int i = 0; i < 2; i++)
#pragma unroll
            for (int j = 0; j < 8; j++)
#pragma unroll
                for (int q = 0; q < 4; q++) acc[i][j][q] = 0.f;

#pragma unroll
        for (int ks = 0; ks < 8; ks++) {
            u32 ah[2][4];
#pragma unroll
            for (int mt = 0; mt < 2; mt++) {
                int aw = (m0w + mt * 16 + r8 + (sub & 1) * 8) * PA2 + (sub >> 1) * 4 + ks * 8;
                LDSM_X4(ah[mt], smb + SCV + aw * 4);
            }
#pragma unroll
            for (int g = 0; g < 4; g++) {
                u32 bh[4], bl[4];
                int bw = (nb + g * 16 + r8 + (sub >> 1) * 8) * PA2 + (sub & 1) * 4 + ks * 8;
                LDSM_X4(bh, smb + XBH + bw * 4);
                LDSM_X4(bl, smb + XBL + bw * 4);
                mma16816(acc[0][2 * g], ah[0], bh[0], bh[1]);
                mma16816(acc[1][2 * g], ah[1], bh[0], bh[1]);
                mma16816(acc[0][2 * g + 1], ah[0], bh[2], bh[3]);
                mma16816(acc[1][2 * g + 1], ah[1], bh[2], bh[3]);
                mma16816(acc[0][2 * g], ah[0], bl[0], bl[1]);
                mma16816(acc[1][2 * g], ah[1], bl[0], bl[1]);
                mma16816(acc[0][2 * g + 1], ah[0], bl[2], bl[3]);
                mma16816(acc[1][2 * g + 1], ah[1], bl[2], bl[3]);
            }
        }

        float* rho = out + 2 * N + D;
#pragma unroll
        for (int mt = 0; mt < 2; mt++)
#pragma unroll
            for (int j = 0; j < 8; j++) {
                int d = m0w + mt * 16 + gr;
                int col = n0 + nb + j * 8 + 2 * gc;
                *(float2*)&rho[(size_t)d * N + col] = make_float2(acc[mt][j][0], acc[mt][j][1]);
                *(float2*)&rho[(size_t)(d + 8) * N + col] =
                    make_float2(acc[mt][j][2], acc[mt][j][3]);
            }
    }
}

// ---------------- K3: y = relu(Dy.lnA)*relu(x_f); 4 rows/warp, MLP 8 ---------
__global__ __launch_bounds__(256) void k_y(const float* __restrict__ Dy,
                                           float* __restrict__ out) {
    __shared__ float sa[D];
    int tid = threadIdx.x, lane = tid & 31, wid = tid >> 5;
    sa[tid] = g_lnA[tid];
    __syncthreads();
    float sreg[8];
#pragma unroll
    for (int j = 0; j < 8; j++) sreg[j] = sa[lane * 8 + j];
    int nbase = blockIdx.x * 32 + wid * 4;
    float4 v0[4], v1[4];
#pragma unroll
    for (int r = 0; r < 4; r++) {
        const float* row = &Dy[(size_t)(nbase + r) * D + lane * 8];
        v0[r] = *(const float4*)row;
        v1[r] = *(const float4*)(row + 4);
    }
#pragma unroll
    for (int r = 0; r < 4; r++) {
        float s = 0.f;
        s = fmaf(v0[r].x, sreg[0], s);
        s = fmaf(v0[r].y, sreg[1], s);
        s = fmaf(v0[r].z, sreg[2], s);
        s = fmaf(v0[r].w, sreg[3], s);
        s = fmaf(v1[r].x, sreg[4], s);
        s = fmaf(v1[r].y, sreg[5], s);
        s = fmaf(v1[r].z, sreg[6], s);
        s = fmaf(v1[r].w, sreg[7], s);
#pragma unroll
        for (int off = 16; off > 0; off >>= 1) s += __shfl_down_sync(0xffffffffu, s, off);
        if (lane == 0)
            out[N + nbase + r] = fmaxf(s, 0.f) * fmaxf(out[nbase + r], 0.f);
    }
}

// ---------------- K4: u[d] = E[d,:].y + (last block) v* = layernorm(u) -------
__global__ __launch_bounds__(256) void k_u(const float* __restrict__ E,
                                           float* __restrict__ out) {
    __shared__ float red[256];
    __shared__ int sflag;
    int d = blockIdx.x, tid = threadIdx.x;
    const float4* e = (const float4*)&E[(size_t)d * N];
    const float4* y = (const float4*)&out[N];
    float s = 0.f;
#pragma unroll 8
    for (int r = 0; r < 16; r++) {
        float4 a = e[tid + 256 * r];
        float4 b = y[tid + 256 * r];
        s = fmaf(a.x, b.x, s);
        s = fmaf(a.y, b.y, s);
        s = fmaf(a.z, b.z, s);
        s = fmaf(a.w, b.w, s);
    }
    red[tid] = s;
    __syncthreads();
    for (int off = 128; off > 0; off >>= 1) {
        if (tid < off) red[tid] += red[tid + off];
        __syncthreads();
    }
    if (tid == 0) {
        g_u[d] = red[0];
        __threadfence();
        sflag = (atomicAdd(&g_ctr2, 1) == 255);
    }
    __syncthreads();
    if (sflag) {
        float a = g_u[tid];
        red[tid] = a;
        __syncthreads();
        for (int off = 128; off > 0; off >>= 1) {
            if (tid < off) red[tid] += red[tid + off];
            __syncthreads();
        }
        float m = red[0] * (1.f / D);
        __syncthreads();
        float c = a - m;
        red[tid] = c * c;
        __syncthreads();
        for (int off = 128; off > 0; off >>= 1) {
            if (tid < off) red[tid] += red[tid + off];
            __syncthreads();
        }
        float sd = sqrtf(red[0] / (float)(D - 1));
        out[2 * N + tid] = c / (sd + 1e-6f);
        if (tid == 0) g_ctr2 = 0;  // reset for next graph replay
    }
}

// ---------------------------------------------------------------------------
extern "C" void kernel_launch(void* const* d_in, const int* in_sizes, int n_in,
                              void* d_out, int out_size) {
    const float* E    = (const float*)d_in[0];
    const float* Dx   = (const float*)d_in[1];
    const float* Dy   = (const float*)d_in[2];
    const float* temb = (const float*)d_in[3];
    const int*   toks = (const int*)d_in[4];
    float* out = (float*)d_out;

    const int SM12 = 208896;
    static int inited = 0;
    if (!inited) {
        cudaFuncSetAttribute(k_gemm12, cudaFuncAttributeMaxDynamicSharedMemorySize, SM12);
        inited = 1;
    }

    k_prep<<<T, 256>>>(temb, toks);
    k_gemm12<<<N / 128, 512, SM12>>>(Dx, out);
    k_y<<<N / 32, 256>>>(Dy, out);
    k_u<<<D, 256>>>(E, out);
}